// round 1
// baseline (speedup 1.0000x reference)
#include <cuda_runtime.h>
#include <math.h>

// Problem constants
#define BB    4
#define CC    256
#define NN    4096      // h*w = 64*64
#define GG    8
#define NHEAD 4
#define DD    64        // head dim
#define EPSV  1e-5f

// Scratch (device globals: no allocations allowed)
__device__ float g_xn [(size_t)BB * CC * NN];        // 16 MB  groupnorm output
__device__ float g_qkv[(size_t)BB * 3 * CC * NN];    // 48 MB  qkv output
__device__ float g_att[(size_t)BB * CC * NN];        // 16 MB  attention output

// ---------------------------------------------------------------------------
// GroupNorm: one block per (b, g). Reduce 32*4096 = 131072 elements, then
// normalize with gn_w/gn_b fused into scale/shift.
// ---------------------------------------------------------------------------
__global__ __launch_bounds__(1024) void gn_kernel(
    const float* __restrict__ x, const float* __restrict__ gw,
    const float* __restrict__ gb, float* __restrict__ xn)
{
    const int b = blockIdx.x >> 3;
    const int g = blockIdx.x & 7;
    const size_t base = ((size_t)(b * CC + g * 32)) * NN;
    const float4* xp = (const float4*)(x + base);
    const int NV = 32 * NN / 4;  // 32768 float4s

    float s = 0.f, ss = 0.f;
    for (int i = threadIdx.x; i < NV; i += blockDim.x) {
        float4 v = xp[i];
        s  += v.x + v.y + v.z + v.w;
        ss += v.x * v.x + v.y * v.y + v.z * v.z + v.w * v.w;
    }
    __shared__ float rs[32], rss[32];
    #pragma unroll
    for (int o = 16; o; o >>= 1) {
        s  += __shfl_down_sync(0xffffffffu, s,  o);
        ss += __shfl_down_sync(0xffffffffu, ss, o);
    }
    int wid = threadIdx.x >> 5, lid = threadIdx.x & 31;
    if (!lid) { rs[wid] = s; rss[wid] = ss; }
    __syncthreads();
    if (threadIdx.x < 32) {
        s = rs[threadIdx.x]; ss = rss[threadIdx.x];
        #pragma unroll
        for (int o = 16; o; o >>= 1) {
            s  += __shfl_down_sync(0xffffffffu, s,  o);
            ss += __shfl_down_sync(0xffffffffu, ss, o);
        }
        if (threadIdx.x == 0) {
            float mean = s * (1.f / 131072.f);
            float var  = ss * (1.f / 131072.f) - mean * mean;
            rs[0] = mean;
            rs[1] = rsqrtf(var + EPSV);
        }
    }
    __syncthreads();
    const float mean = rs[0], rstd = rs[1];
    float4* outp = (float4*)(xn + base);
    for (int i = threadIdx.x; i < NV; i += blockDim.x) {
        int ch = g * 32 + (i >> 10);   // 1024 float4s per channel
        float a  = gw[ch] * rstd;
        float bb = gb[ch] - mean * a;
        float4 v = xp[i];
        v.x = v.x * a + bb; v.y = v.y * a + bb;
        v.z = v.z * a + bb; v.w = v.w * a + bb;
        outp[i] = v;
    }
}

// ---------------------------------------------------------------------------
// Batched SGEMM:  C[b] = A[M,K] * B[b][K,NN] + bias  (+ residual)
// Block tile 64x64, BK=16, 256 threads, 4x4 register tile per thread.
// ---------------------------------------------------------------------------
__global__ __launch_bounds__(256) void gemm_kernel(
    const float* __restrict__ A, const float* __restrict__ Bm,
    const float* __restrict__ bias, const float* __restrict__ res,
    float* __restrict__ C, int M, int K)
{
    __shared__ float As[16][68];   // [k][m], pad 68 keeps float4 reads aligned
    __shared__ float Bs[16][64];   // [k][n]

    const int bz = blockIdx.z;
    const float* Bp = Bm + (size_t)bz * K * NN;
    float*       Cp = C  + (size_t)bz * M * NN;
    const float* Rp = res ? res + (size_t)bz * M * NN : nullptr;

    const int n0 = blockIdx.x * 64;
    const int m0 = blockIdx.y * 64;
    const int tid = threadIdx.x;
    const int tx = tid & 15, ty = tid >> 4;
    const int arow = tid >> 2, ac4 = tid & 3;
    const int brow = tid >> 4, bc4 = tid & 15;

    float acc[4][4] = {};

    for (int kt = 0; kt < K; kt += 16) {
        float4 av = *(const float4*)&A[(size_t)(m0 + arow) * K + kt + ac4 * 4];
        As[ac4 * 4 + 0][arow] = av.x;
        As[ac4 * 4 + 1][arow] = av.y;
        As[ac4 * 4 + 2][arow] = av.z;
        As[ac4 * 4 + 3][arow] = av.w;
        *(float4*)&Bs[brow][bc4 * 4] =
            *(const float4*)&Bp[(size_t)(kt + brow) * NN + n0 + bc4 * 4];
        __syncthreads();
        #pragma unroll
        for (int k = 0; k < 16; k++) {
            float4 a = *(const float4*)&As[k][ty * 4];
            float4 b = *(const float4*)&Bs[k][tx * 4];
            acc[0][0] += a.x * b.x; acc[0][1] += a.x * b.y;
            acc[0][2] += a.x * b.z; acc[0][3] += a.x * b.w;
            acc[1][0] += a.y * b.x; acc[1][1] += a.y * b.y;
            acc[1][2] += a.y * b.z; acc[1][3] += a.y * b.w;
            acc[2][0] += a.z * b.x; acc[2][1] += a.z * b.y;
            acc[2][2] += a.z * b.z; acc[2][3] += a.z * b.w;
            acc[3][0] += a.w * b.x; acc[3][1] += a.w * b.y;
            acc[3][2] += a.w * b.z; acc[3][3] += a.w * b.w;
        }
        __syncthreads();
    }

    #pragma unroll
    for (int i = 0; i < 4; i++) {
        const int m = m0 + ty * 4 + i;
        const float bi = bias[m];
        float4 v = make_float4(acc[i][0] + bi, acc[i][1] + bi,
                               acc[i][2] + bi, acc[i][3] + bi);
        const size_t off = (size_t)m * NN + n0 + tx * 4;
        if (Rp) {
            float4 r = *(const float4*)&Rp[off];
            v.x += r.x; v.y += r.y; v.z += r.z; v.w += r.w;
        }
        *(float4*)&Cp[off] = v;
    }
}

// ---------------------------------------------------------------------------
// Flash attention (fp32). One block = one (b, head, 64-query tile).
// 64 threads; each thread owns one query row: Q (prescaled) + O accumulator
// in registers, K/V tiles in smem in [d][j] layout (broadcast LDS.128 reads).
// Online softmax in 16-wide chunks (rolled chunk loop limits I$ footprint).
// ---------------------------------------------------------------------------
__global__ __launch_bounds__(64) void attn_kernel(
    const float* __restrict__ qkv, float* __restrict__ out)
{
    __shared__ float Ks[64][64];
    __shared__ float Vs[64][64];

    const int bh = blockIdx.y;            // 0..15
    const int b  = bh >> 2;
    const int hh = bh & 3;
    const int qb = blockIdx.x * 64;
    const int tid = threadIdx.x;

    const float* qp = qkv + ((size_t)b * (3 * CC) + hh * DD) * NN;
    const float* kp = qp + (size_t)CC * NN;
    const float* vp = qp + (size_t)(2 * CC) * NN;

    const int iq = qb + tid;
    float Q[64];
    #pragma unroll
    for (int d = 0; d < 64; d++) Q[d] = qp[(size_t)d * NN + iq] * 0.125f;

    float O[64];
    #pragma unroll
    for (int d = 0; d < 64; d++) O[d] = 0.f;
    float m = -INFINITY, l = 0.f;

    for (int jt = 0; jt < NN; jt += 64) {
        __syncthreads();
        #pragma unroll 8
        for (int d = 0; d < 64; d++) {
            Ks[d][tid] = kp[(size_t)d * NN + jt + tid];
            Vs[d][tid] = vp[(size_t)d * NN + jt + tid];
        }
        __syncthreads();

        #pragma unroll 1
        for (int ch = 0; ch < 4; ch++) {
            const float* ksc = &Ks[0][0] + ch * 16;
            const float* vsc = &Vs[0][0] + ch * 16;
            float s[16];
            #pragma unroll
            for (int j = 0; j < 16; j++) s[j] = 0.f;
            #pragma unroll
            for (int d = 0; d < 64; d++) {
                const float qd = Q[d];
                #pragma unroll
                for (int j4 = 0; j4 < 4; j4++) {
                    float4 kk = *(const float4*)(ksc + d * 64 + j4 * 4);
                    s[j4 * 4 + 0] += qd * kk.x;
                    s[j4 * 4 + 1] += qd * kk.y;
                    s[j4 * 4 + 2] += qd * kk.z;
                    s[j4 * 4 + 3] += qd * kk.w;
                }
            }
            float mt = s[0];
            #pragma unroll
            for (int j = 1; j < 16; j++) mt = fmaxf(mt, s[j]);
            const float mnew = fmaxf(m, mt);
            const float corr = __expf(m - mnew);
            m = mnew;
            float ps = 0.f;
            #pragma unroll
            for (int j = 0; j < 16; j++) { s[j] = __expf(s[j] - mnew); ps += s[j]; }
            l = l * corr + ps;
            #pragma unroll
            for (int d = 0; d < 64; d++) {
                float o = O[d] * corr;
                #pragma unroll
                for (int j4 = 0; j4 < 4; j4++) {
                    float4 vv = *(const float4*)(vsc + d * 64 + j4 * 4);
                    o += s[j4 * 4 + 0] * vv.x + s[j4 * 4 + 1] * vv.y +
                         s[j4 * 4 + 2] * vv.z + s[j4 * 4 + 3] * vv.w;
                }
                O[d] = o;
            }
        }
    }

    const float inv = 1.f / l;
    float* op = out + ((size_t)b * CC + hh * DD) * NN;
    #pragma unroll
    for (int d = 0; d < 64; d++) op[(size_t)d * NN + iq] = O[d] * inv;
}

// ---------------------------------------------------------------------------
// Launch
// ---------------------------------------------------------------------------
extern "C" void kernel_launch(void* const* d_in, const int* in_sizes, int n_in,
                              void* d_out, int out_size)
{
    const float* x      = (const float*)d_in[0];
    const float* gn_w   = (const float*)d_in[1];
    const float* gn_b   = (const float*)d_in[2];
    const float* qkv_w  = (const float*)d_in[3];
    const float* qkv_b  = (const float*)d_in[4];
    const float* proj_w = (const float*)d_in[5];
    const float* proj_b = (const float*)d_in[6];
    float* out = (float*)d_out;

    void *p_xn, *p_qkv, *p_att;
    cudaGetSymbolAddress(&p_xn,  g_xn);
    cudaGetSymbolAddress(&p_qkv, g_qkv);
    cudaGetSymbolAddress(&p_att, g_att);
    float* xn  = (float*)p_xn;
    float* qkv = (float*)p_qkv;
    float* att = (float*)p_att;

    // 1. GroupNorm
    gn_kernel<<<BB * GG, 1024>>>(x, gn_w, gn_b, xn);

    // 2. QKV GEMM: [768,256] x [256,4096] per batch
    {
        dim3 grid(NN / 64, (3 * CC) / 64, BB);
        gemm_kernel<<<grid, 256>>>(qkv_w, xn, qkv_b, nullptr, qkv, 3 * CC, CC);
    }

    // 3. Attention
    {
        dim3 grid(NN / 64, BB * NHEAD);
        attn_kernel<<<grid, 64>>>(qkv, att);
    }

    // 4. Proj GEMM + bias + residual
    {
        dim3 grid(NN / 64, CC / 64, BB);
        gemm_kernel<<<grid, 256>>>(proj_w, att, proj_b, x, out, CC, CC);
    }
}

// round 3
// speedup vs baseline: 4.6524x; 4.6524x over previous
#include <cuda_runtime.h>
#include <math.h>

// Problem constants
#define BB    4
#define CC    256
#define NN    4096      // h*w = 64*64
#define GG    8
#define NHEAD 4
#define DD    64        // head dim
#define EPSV  1e-5f

// Scratch (device globals: no allocations allowed)
__device__ float g_xn [(size_t)BB * CC * NN];        // 16 MB  groupnorm output
__device__ float g_qkv[(size_t)BB * 3 * CC * NN];    // 48 MB  qkv output
__device__ float g_att[(size_t)BB * CC * NN];        // 16 MB  attention output

// ---------------------------------------------------------------------------
// GroupNorm: one block per (b, g).
// ---------------------------------------------------------------------------
__global__ __launch_bounds__(1024) void gn_kernel(
    const float* __restrict__ x, const float* __restrict__ gw,
    const float* __restrict__ gb, float* __restrict__ xn)
{
    const int b = blockIdx.x >> 3;
    const int g = blockIdx.x & 7;
    const size_t base = ((size_t)(b * CC + g * 32)) * NN;
    const float4* xp = (const float4*)(x + base);
    const int NV = 32 * NN / 4;  // 32768 float4s

    float s = 0.f, ss = 0.f;
    for (int i = threadIdx.x; i < NV; i += blockDim.x) {
        float4 v = xp[i];
        s  += v.x + v.y + v.z + v.w;
        ss += v.x * v.x + v.y * v.y + v.z * v.z + v.w * v.w;
    }
    __shared__ float rs[32], rss[32];
    #pragma unroll
    for (int o = 16; o; o >>= 1) {
        s  += __shfl_down_sync(0xffffffffu, s,  o);
        ss += __shfl_down_sync(0xffffffffu, ss, o);
    }
    int wid = threadIdx.x >> 5, lid = threadIdx.x & 31;
    if (!lid) { rs[wid] = s; rss[wid] = ss; }
    __syncthreads();
    if (threadIdx.x < 32) {
        s = rs[threadIdx.x]; ss = rss[threadIdx.x];
        #pragma unroll
        for (int o = 16; o; o >>= 1) {
            s  += __shfl_down_sync(0xffffffffu, s,  o);
            ss += __shfl_down_sync(0xffffffffu, ss, o);
        }
        if (threadIdx.x == 0) {
            float mean = s * (1.f / 131072.f);
            float var  = ss * (1.f / 131072.f) - mean * mean;
            rs[0] = mean;
            rs[1] = rsqrtf(var + EPSV);
        }
    }
    __syncthreads();
    const float mean = rs[0], rstd = rs[1];
    float4* outp = (float4*)(xn + base);
    for (int i = threadIdx.x; i < NV; i += blockDim.x) {
        int ch = g * 32 + (i >> 10);
        float a  = gw[ch] * rstd;
        float bb = gb[ch] - mean * a;
        float4 v = xp[i];
        v.x = v.x * a + bb; v.y = v.y * a + bb;
        v.z = v.z * a + bb; v.w = v.w * a + bb;
        outp[i] = v;
    }
}

// ---------------------------------------------------------------------------
// Batched SGEMM:  C[b] = A[M,K] * B[b][K,NN] + bias  (+ residual)
// ---------------------------------------------------------------------------
__global__ __launch_bounds__(256) void gemm_kernel(
    const float* __restrict__ A, const float* __restrict__ Bm,
    const float* __restrict__ bias, const float* __restrict__ res,
    float* __restrict__ C, int M, int K)
{
    __shared__ float As[16][68];
    __shared__ float Bs[16][64];

    const int bz = blockIdx.z;
    const float* Bp = Bm + (size_t)bz * K * NN;
    float*       Cp = C  + (size_t)bz * M * NN;
    const float* Rp = res ? res + (size_t)bz * M * NN : nullptr;

    const int n0 = blockIdx.x * 64;
    const int m0 = blockIdx.y * 64;
    const int tid = threadIdx.x;
    const int tx = tid & 15, ty = tid >> 4;
    const int arow = tid >> 2, ac4 = tid & 3;
    const int brow = tid >> 4, bc4 = tid & 15;

    float acc[4][4] = {};

    for (int kt = 0; kt < K; kt += 16) {
        float4 av = *(const float4*)&A[(size_t)(m0 + arow) * K + kt + ac4 * 4];
        As[ac4 * 4 + 0][arow] = av.x;
        As[ac4 * 4 + 1][arow] = av.y;
        As[ac4 * 4 + 2][arow] = av.z;
        As[ac4 * 4 + 3][arow] = av.w;
        *(float4*)&Bs[brow][bc4 * 4] =
            *(const float4*)&Bp[(size_t)(kt + brow) * NN + n0 + bc4 * 4];
        __syncthreads();
        #pragma unroll
        for (int k = 0; k < 16; k++) {
            float4 a = *(const float4*)&As[k][ty * 4];
            float4 b = *(const float4*)&Bs[k][tx * 4];
            acc[0][0] += a.x * b.x; acc[0][1] += a.x * b.y;
            acc[0][2] += a.x * b.z; acc[0][3] += a.x * b.w;
            acc[1][0] += a.y * b.x; acc[1][1] += a.y * b.y;
            acc[1][2] += a.y * b.z; acc[1][3] += a.y * b.w;
            acc[2][0] += a.z * b.x; acc[2][1] += a.z * b.y;
            acc[2][2] += a.z * b.z; acc[2][3] += a.z * b.w;
            acc[3][0] += a.w * b.x; acc[3][1] += a.w * b.y;
            acc[3][2] += a.w * b.z; acc[3][3] += a.w * b.w;
        }
        __syncthreads();
    }

    #pragma unroll
    for (int i = 0; i < 4; i++) {
        const int m = m0 + ty * 4 + i;
        const float bi = bias[m];
        float4 v = make_float4(acc[i][0] + bi, acc[i][1] + bi,
                               acc[i][2] + bi, acc[i][3] + bi);
        const size_t off = (size_t)m * NN + n0 + tx * 4;
        if (Rp) {
            float4 r = *(const float4*)&Rp[off];
            v.x += r.x; v.y += r.y; v.z += r.z; v.w += r.w;
        }
        *(float4*)&Cp[off] = v;
    }
}

// ---------------------------------------------------------------------------
// Flash attention on tensor pipe: mma.sync m16n8k8 tf32, fp32 accumulate.
// One block = (b, head, 64-query tile). 4 warps, each owns 16 query rows.
// Q/K/V staged in smem in natural [d][token] layout (coalesced + directly the
// col-major B operand layout). P re-layout C-frag -> A-frag via smem (reuses
// the Q buffer; per-warp-private rows, __syncwarp only).
// ---------------------------------------------------------------------------
#define LDPAD 68
#define ATTN_SMEM_BYTES (3 * 64 * LDPAD * 4)

__device__ __forceinline__ unsigned f2tf32(float x) {
    unsigned r;
    asm("cvt.rna.tf32.f32 %0, %1;" : "=r"(r) : "f"(x));
    return r;
}

__device__ __forceinline__ void mma_tf32(float c[4], const unsigned a[4],
                                         unsigned b0, unsigned b1) {
    asm volatile(
        "mma.sync.aligned.m16n8k8.row.col.f32.tf32.tf32.f32 "
        "{%0,%1,%2,%3}, {%4,%5,%6,%7}, {%8,%9}, {%0,%1,%2,%3};"
        : "+f"(c[0]), "+f"(c[1]), "+f"(c[2]), "+f"(c[3])
        : "r"(a[0]), "r"(a[1]), "r"(a[2]), "r"(a[3]), "r"(b0), "r"(b1));
}

__global__ __launch_bounds__(128) void attn_mma_kernel(
    const float* __restrict__ qkv, float* __restrict__ out)
{
    extern __shared__ float smem[];
    float* Ks  = smem;                  // [64][68]  tf32 bits
    float* Vs  = smem + 64 * LDPAD;     // [64][68]
    float* QPs = smem + 2 * 64 * LDPAD; // [64][68]  Q tile, then P buffer

    const int tid  = threadIdx.x;
    const int w    = tid >> 5;
    const int lane = tid & 31;
    const int g    = lane >> 2;   // 0..7
    const int tig  = lane & 3;    // 0..3

    const int bh = blockIdx.y;
    const int b  = bh >> 2;
    const int hh = bh & 3;
    const int qb = blockIdx.x * 64;

    const float* qp = qkv + ((size_t)b * (3 * CC) + hh * DD) * NN;
    const float* kp = qp + (size_t)CC * NN;
    const float* vp = qp + (size_t)(2 * CC) * NN;

    // --- Load Q tile (scaled, tf32) into QPs [d][m] ---
    #pragma unroll
    for (int i = 0; i < 8; i++) {
        int lin = tid + i * 128;       // 0..1023
        int row = lin >> 4;            // d
        int c4  = lin & 15;
        float4 v = *(const float4*)&qp[(size_t)row * NN + qb + c4 * 4];
        unsigned u0 = f2tf32(v.x * 0.125f), u1 = f2tf32(v.y * 0.125f);
        unsigned u2 = f2tf32(v.z * 0.125f), u3 = f2tf32(v.w * 0.125f);
        float4 o = make_float4(__uint_as_float(u0), __uint_as_float(u1),
                               __uint_as_float(u2), __uint_as_float(u3));
        *(float4*)&QPs[row * LDPAD + c4 * 4] = o;
    }
    __syncthreads();

    // --- Q A-fragments: resident for whole kernel (32 regs) ---
    unsigned qa[8][4];
    const unsigned* QPu = (const unsigned*)QPs;
    #pragma unroll
    for (int kt = 0; kt < 8; kt++) {
        int d0 = kt * 8 + tig;
        int m0 = w * 16 + g;
        qa[kt][0] = QPu[d0 * LDPAD + m0];
        qa[kt][1] = QPu[d0 * LDPAD + m0 + 8];
        qa[kt][2] = QPu[(d0 + 4) * LDPAD + m0];
        qa[kt][3] = QPu[(d0 + 4) * LDPAD + m0 + 8];
    }
    __syncthreads();   // everyone done reading Q; QPs becomes P buffer

    float O[8][4];
    #pragma unroll
    for (int t = 0; t < 8; t++)
        #pragma unroll
        for (int r = 0; r < 4; r++) O[t][r] = 0.f;
    float m0r = -INFINITY, m1r = -INFINITY, l0 = 0.f, l1 = 0.f;

    const unsigned* Ku = (const unsigned*)Ks;
    const unsigned* Vu = (const unsigned*)Vs;
    unsigned* Pu = (unsigned*)QPs;

    for (int jt = 0; jt < NN; jt += 64) {
        __syncthreads();
        // --- Load K,V tiles (tf32) into [d][token] layout ---
        #pragma unroll
        for (int i = 0; i < 8; i++) {
            int lin = tid + i * 128;
            int row = lin >> 4;
            int c4  = lin & 15;
            float4 kv = *(const float4*)&kp[(size_t)row * NN + jt + c4 * 4];
            float4 vv = *(const float4*)&vp[(size_t)row * NN + jt + c4 * 4];
            float4 ko = make_float4(
                __uint_as_float(f2tf32(kv.x)), __uint_as_float(f2tf32(kv.y)),
                __uint_as_float(f2tf32(kv.z)), __uint_as_float(f2tf32(kv.w)));
            float4 vo = make_float4(
                __uint_as_float(f2tf32(vv.x)), __uint_as_float(f2tf32(vv.y)),
                __uint_as_float(f2tf32(vv.z)), __uint_as_float(f2tf32(vv.w)));
            *(float4*)&Ks[row * LDPAD + c4 * 4] = ko;
            *(float4*)&Vs[row * LDPAD + c4 * 4] = vo;
        }
        __syncthreads();

        // --- S = Q K^T : 8 n-tiles x 8 k-tiles of m16n8k8 ---
        float sc[8][4];
        #pragma unroll
        for (int t = 0; t < 8; t++) {
            sc[t][0] = sc[t][1] = sc[t][2] = sc[t][3] = 0.f;
            #pragma unroll
            for (int kt = 0; kt < 8; kt++) {
                unsigned b0 = Ku[(kt * 8 + tig) * LDPAD + t * 8 + g];
                unsigned b1 = Ku[(kt * 8 + tig + 4) * LDPAD + t * 8 + g];
                mma_tf32(sc[t], qa[kt], b0, b1);
            }
        }

        // --- Online softmax over the 64-wide tile ---
        float ml0 = -INFINITY, ml1 = -INFINITY;
        #pragma unroll
        for (int t = 0; t < 8; t++) {
            ml0 = fmaxf(ml0, fmaxf(sc[t][0], sc[t][1]));
            ml1 = fmaxf(ml1, fmaxf(sc[t][2], sc[t][3]));
        }
        ml0 = fmaxf(ml0, __shfl_xor_sync(0xffffffffu, ml0, 1));
        ml0 = fmaxf(ml0, __shfl_xor_sync(0xffffffffu, ml0, 2));
        ml1 = fmaxf(ml1, __shfl_xor_sync(0xffffffffu, ml1, 1));
        ml1 = fmaxf(ml1, __shfl_xor_sync(0xffffffffu, ml1, 2));

        const float mn0 = fmaxf(m0r, ml0);
        const float mn1 = fmaxf(m1r, ml1);
        const float corr0 = __expf(m0r - mn0);
        const float corr1 = __expf(m1r - mn1);
        m0r = mn0; m1r = mn1;

        float ls0 = 0.f, ls1 = 0.f;
        const int pr0 = (w * 16 + g) * LDPAD;
        const int pr1 = (w * 16 + g + 8) * LDPAD;
        #pragma unroll
        for (int t = 0; t < 8; t++) {
            float p0 = __expf(sc[t][0] - mn0);
            float p1 = __expf(sc[t][1] - mn0);
            float p2 = __expf(sc[t][2] - mn1);
            float p3 = __expf(sc[t][3] - mn1);
            ls0 += p0 + p1; ls1 += p2 + p3;
            uint2 a01 = make_uint2(f2tf32(p0), f2tf32(p1));
            uint2 a23 = make_uint2(f2tf32(p2), f2tf32(p3));
            *(uint2*)&Pu[pr0 + t * 8 + 2 * tig] = a01;
            *(uint2*)&Pu[pr1 + t * 8 + 2 * tig] = a23;
        }
        ls0 += __shfl_xor_sync(0xffffffffu, ls0, 1);
        ls0 += __shfl_xor_sync(0xffffffffu, ls0, 2);
        ls1 += __shfl_xor_sync(0xffffffffu, ls1, 1);
        ls1 += __shfl_xor_sync(0xffffffffu, ls1, 2);
        l0 = l0 * corr0 + ls0;
        l1 = l1 * corr1 + ls1;

        #pragma unroll
        for (int t = 0; t < 8; t++) {
            O[t][0] *= corr0; O[t][1] *= corr0;
            O[t][2] *= corr1; O[t][3] *= corr1;
        }
        __syncwarp();   // our warp's P rows visible to our own A-frag loads

        // --- O += P V^T : A from Ps, B from Vs ---
        #pragma unroll
        for (int kn = 0; kn < 8; kn++) {
            unsigned pa[4];
            pa[0] = Pu[pr0 + kn * 8 + tig];
            pa[1] = Pu[pr1 + kn * 8 + tig];
            pa[2] = Pu[pr0 + kn * 8 + tig + 4];
            pa[3] = Pu[pr1 + kn * 8 + tig + 4];
            #pragma unroll
            for (int dt = 0; dt < 8; dt++) {
                unsigned b0 = Vu[(dt * 8 + g) * LDPAD + kn * 8 + tig];
                unsigned b1 = Vu[(dt * 8 + g) * LDPAD + kn * 8 + tig + 4];
                mma_tf32(O[dt], pa, b0, b1);
            }
        }
        __syncwarp();   // done reading P before next iter overwrites (same warp)
    }

    // --- Epilogue: normalize + store (out layout [d][token]) ---
    const float inv0 = 1.f / l0;
    const float inv1 = 1.f / l1;
    float* op = out + ((size_t)b * CC + hh * DD) * NN;
    const int tok0 = qb + w * 16 + g;
    const int tok1 = tok0 + 8;
    #pragma unroll
    for (int dt = 0; dt < 8; dt++) {
        int d = dt * 8 + 2 * tig;
        op[(size_t)d * NN + tok0]       = O[dt][0] * inv0;
        op[(size_t)(d + 1) * NN + tok0] = O[dt][1] * inv0;
        op[(size_t)d * NN + tok1]       = O[dt][2] * inv1;
        op[(size_t)(d + 1) * NN + tok1] = O[dt][3] * inv1;
    }
}

// ---------------------------------------------------------------------------
// Launch
// ---------------------------------------------------------------------------
extern "C" void kernel_launch(void* const* d_in, const int* in_sizes, int n_in,
                              void* d_out, int out_size)
{
    const float* x      = (const float*)d_in[0];
    const float* gn_w   = (const float*)d_in[1];
    const float* gn_b   = (const float*)d_in[2];
    const float* qkv_w  = (const float*)d_in[3];
    const float* qkv_b  = (const float*)d_in[4];
    const float* proj_w = (const float*)d_in[5];
    const float* proj_b = (const float*)d_in[6];
    float* out = (float*)d_out;

    void *p_xn, *p_qkv, *p_att;
    cudaGetSymbolAddress(&p_xn,  g_xn);
    cudaGetSymbolAddress(&p_qkv, g_qkv);
    cudaGetSymbolAddress(&p_att, g_att);
    float* xn  = (float*)p_xn;
    float* qkv = (float*)p_qkv;
    float* att = (float*)p_att;

    cudaFuncSetAttribute(attn_mma_kernel,
                         cudaFuncAttributeMaxDynamicSharedMemorySize,
                         ATTN_SMEM_BYTES);

    // 1. GroupNorm
    gn_kernel<<<BB * GG, 1024>>>(x, gn_w, gn_b, xn);

    // 2. QKV GEMM: [768,256] x [256,4096] per batch
    {
        dim3 grid(NN / 64, (3 * CC) / 64, BB);
        gemm_kernel<<<grid, 256>>>(qkv_w, xn, qkv_b, nullptr, qkv, 3 * CC, CC);
    }

    // 3. Attention (tensor pipe, tf32)
    {
        dim3 grid(NN / 64, BB * NHEAD);
        attn_mma_kernel<<<grid, 128, ATTN_SMEM_BYTES>>>(qkv, att);
    }

    // 4. Proj GEMM + bias + residual
    {
        dim3 grid(NN / 64, CC / 64, BB);
        gemm_kernel<<<grid, 256>>>(proj_w, att, proj_b, x, out, CC, CC);
    }
}

// round 5
// speedup vs baseline: 6.1019x; 1.3116x over previous
#include <cuda_runtime.h>
#include <math.h>

// Problem constants
#define BB    4
#define CC    256
#define NN    4096      // h*w = 64*64
#define GG    8
#define NHEAD 4
#define DD    64        // head dim
#define EPSV  1e-5f

// Scratch (device globals: no allocations allowed)
__device__ float g_xn [(size_t)BB * CC * NN];        // 16 MB  groupnorm output (tf32-rounded)
__device__ float g_qkv[(size_t)BB * 3 * CC * NN];    // 48 MB  qkv output (tf32-rounded)
__device__ float g_att[(size_t)BB * CC * NN];        // 16 MB  attention output (tf32-rounded)
__device__ float g_wq [(size_t)3 * CC * CC];         // qkv_w tf32-rounded
__device__ float g_wp [(size_t)CC * CC];             // proj_w tf32-rounded

__device__ __forceinline__ unsigned f2tf32(float x) {
    unsigned r;
    asm("cvt.rna.tf32.f32 %0, %1;" : "=r"(r) : "f"(x));
    return r;
}
__device__ __forceinline__ float tf32r(float x) {
    return __uint_as_float(f2tf32(x));
}

__device__ __forceinline__ void mma_tf32(float c[4], const unsigned a[4],
                                         unsigned b0, unsigned b1) {
    asm volatile(
        "mma.sync.aligned.m16n8k8.row.col.f32.tf32.tf32.f32 "
        "{%0,%1,%2,%3}, {%4,%5,%6,%7}, {%8,%9}, {%0,%1,%2,%3};"
        : "+f"(c[0]), "+f"(c[1]), "+f"(c[2]), "+f"(c[3])
        : "r"(a[0]), "r"(a[1]), "r"(a[2]), "r"(a[3]), "r"(b0), "r"(b1));
}

// ---------------------------------------------------------------------------
// Weight conversion: round qkv_w and proj_w to tf32 once.
// ---------------------------------------------------------------------------
__global__ __launch_bounds__(256) void wconv_kernel(
    const float* __restrict__ qkv_w, const float* __restrict__ proj_w,
    float* __restrict__ wq, float* __restrict__ wp)
{
    int i = blockIdx.x * 256 + threadIdx.x;
    if (i < 3 * CC * CC) wq[i] = tf32r(qkv_w[i]);
    if (i < CC * CC)     wp[i] = tf32r(proj_w[i]);
}

// ---------------------------------------------------------------------------
// GroupNorm: one block per (b, g). Output rounded to tf32.
// ---------------------------------------------------------------------------
__global__ __launch_bounds__(1024) void gn_kernel(
    const float* __restrict__ x, const float* __restrict__ gw,
    const float* __restrict__ gb, float* __restrict__ xn)
{
    const int b = blockIdx.x >> 3;
    const int g = blockIdx.x & 7;
    const size_t base = ((size_t)(b * CC + g * 32)) * NN;
    const float4* xp = (const float4*)(x + base);
    const int NV = 32 * NN / 4;  // 32768 float4s

    float s = 0.f, ss = 0.f;
    for (int i = threadIdx.x; i < NV; i += blockDim.x) {
        float4 v = xp[i];
        s  += v.x + v.y + v.z + v.w;
        ss += v.x * v.x + v.y * v.y + v.z * v.z + v.w * v.w;
    }
    __shared__ float rs[32], rss[32];
    #pragma unroll
    for (int o = 16; o; o >>= 1) {
        s  += __shfl_down_sync(0xffffffffu, s,  o);
        ss += __shfl_down_sync(0xffffffffu, ss, o);
    }
    int wid = threadIdx.x >> 5, lid = threadIdx.x & 31;
    if (!lid) { rs[wid] = s; rss[wid] = ss; }
    __syncthreads();
    if (threadIdx.x < 32) {
        s = rs[threadIdx.x]; ss = rss[threadIdx.x];
        #pragma unroll
        for (int o = 16; o; o >>= 1) {
            s  += __shfl_down_sync(0xffffffffu, s,  o);
            ss += __shfl_down_sync(0xffffffffu, ss, o);
        }
        if (threadIdx.x == 0) {
            float mean = s * (1.f / 131072.f);
            float var  = ss * (1.f / 131072.f) - mean * mean;
            rs[0] = mean;
            rs[1] = rsqrtf(var + EPSV);
        }
    }
    __syncthreads();
    const float mean = rs[0], rstd = rs[1];
    float4* outp = (float4*)(xn + base);
    for (int i = threadIdx.x; i < NV; i += blockDim.x) {
        int ch = g * 32 + (i >> 10);
        float a  = gw[ch] * rstd;
        float bb = gb[ch] - mean * a;
        float4 v = xp[i];
        v.x = tf32r(v.x * a + bb); v.y = tf32r(v.y * a + bb);
        v.z = tf32r(v.z * a + bb); v.w = tf32r(v.w * a + bb);
        outp[i] = v;
    }
}

// ---------------------------------------------------------------------------
// tf32 MMA GEMM: C[b] = W[M,256] x Act[b][256,4096] + bias (+res).
// BM=64, BN=128, BK=32. 256 threads / 8 warps, warp tile m32 x n32.
// W and Act are pre-rounded to tf32 -> mainloop is pure LDS + HMMA.
// Conflict-free pads: As 36, Bs 132.
// ---------------------------------------------------------------------------
__global__ __launch_bounds__(256) void gemm_tf32_kernel(
    const float* __restrict__ A, const float* __restrict__ Bm,
    const float* __restrict__ bias, const float* __restrict__ res,
    float* __restrict__ C, int M, int round_out)
{
    __shared__ float As[64][36];
    __shared__ float Bs[32][132];

    const int bz = blockIdx.z;
    const float* Bp = Bm + (size_t)bz * CC * NN;
    float*       Cp = C  + (size_t)bz * M * NN;
    const float* Rp = res ? res + (size_t)bz * M * NN : nullptr;

    const int n0 = blockIdx.x * 128;
    const int m0 = blockIdx.y * 64;
    const int tid = threadIdx.x;
    const int w = tid >> 5, lane = tid & 31;
    const int g = lane >> 2, tig = lane & 3;
    const int wm = (w >> 2) * 32;   // 0 or 32
    const int wn = (w & 3) * 32;    // 0,32,64,96

    float acc[2][4][4] = {};

    for (int k0 = 0; k0 < CC; k0 += 32) {
        __syncthreads();
        #pragma unroll
        for (int i = 0; i < 2; i++) {
            int lin = tid + i * 256;
            int r = lin >> 3, c4 = lin & 7;
            *(float4*)&As[r][c4 * 4] =
                *(const float4*)&A[(size_t)(m0 + r) * CC + k0 + c4 * 4];
        }
        #pragma unroll
        for (int i = 0; i < 4; i++) {
            int lin = tid + i * 256;
            int r = lin >> 5, c4 = lin & 31;
            *(float4*)&Bs[r][c4 * 4] =
                *(const float4*)&Bp[(size_t)(k0 + r) * NN + n0 + c4 * 4];
        }
        __syncthreads();

        #pragma unroll
        for (int ks = 0; ks < 4; ks++) {
            unsigned a[2][4];
            #pragma unroll
            for (int mt = 0; mt < 2; mt++) {
                a[mt][0] = __float_as_uint(As[wm + mt * 16 + g    ][ks * 8 + tig]);
                a[mt][1] = __float_as_uint(As[wm + mt * 16 + g + 8][ks * 8 + tig]);
                a[mt][2] = __float_as_uint(As[wm + mt * 16 + g    ][ks * 8 + tig + 4]);
                a[mt][3] = __float_as_uint(As[wm + mt * 16 + g + 8][ks * 8 + tig + 4]);
            }
            #pragma unroll
            for (int nt = 0; nt < 4; nt++) {
                unsigned b0 = __float_as_uint(Bs[ks * 8 + tig    ][wn + nt * 8 + g]);
                unsigned b1 = __float_as_uint(Bs[ks * 8 + tig + 4][wn + nt * 8 + g]);
                mma_tf32(acc[0][nt], a[0], b0, b1);
                mma_tf32(acc[1][nt], a[1], b0, b1);
            }
        }
    }

    #pragma unroll
    for (int mt = 0; mt < 2; mt++) {
        #pragma unroll
        for (int half = 0; half < 2; half++) {
            const int m = m0 + wm + mt * 16 + g + half * 8;
            const float bi = bias[m];
            #pragma unroll
            for (int nt = 0; nt < 4; nt++) {
                float v0 = acc[mt][nt][half * 2 + 0] + bi;
                float v1 = acc[mt][nt][half * 2 + 1] + bi;
                const size_t off = (size_t)m * NN + n0 + wn + nt * 8 + 2 * tig;
                if (Rp) {
                    float2 r = *(const float2*)&Rp[off];
                    v0 += r.x; v1 += r.y;
                }
                if (round_out) { v0 = tf32r(v0); v1 = tf32r(v1); }
                *(float2*)&Cp[off] = make_float2(v0, v1);
            }
        }
    }
}

// ---------------------------------------------------------------------------
// Flash attention, tensor pipe (mma m16n8k8 tf32). One block = (b, head,
// 64-query tile), 4 warps x 16 rows. Inputs pre-rounded to tf32.
// Pads: K=72 (S-phase B-frag loads conflict-free), V=68 (PV conflict-free).
// ---------------------------------------------------------------------------
#define KPAD 72
#define VPAD 68
#define PPAD 68
#define ATTN_SMEM_BYTES ((64 * KPAD + 64 * VPAD + 64 * PPAD) * 4)

__global__ __launch_bounds__(128) void attn_mma_kernel(
    const float* __restrict__ qkv, float* __restrict__ out)
{
    extern __shared__ float smem[];
    float* Ks  = smem;                            // [64][72]
    float* Vs  = smem + 64 * KPAD;                // [64][68]
    float* QPs = smem + 64 * KPAD + 64 * VPAD;    // [64][68] Q tile then P

    const int tid  = threadIdx.x;
    const int w    = tid >> 5;
    const int lane = tid & 31;
    const int g    = lane >> 2;
    const int tig  = lane & 3;

    const int bh = blockIdx.y;
    const int b  = bh >> 2;
    const int hh = bh & 3;
    const int qb = blockIdx.x * 64;

    const float* qp = qkv + ((size_t)b * (3 * CC) + hh * DD) * NN;
    const float* kp = qp + (size_t)CC * NN;
    const float* vp = qp + (size_t)(2 * CC) * NN;

    // --- Load Q tile (x 0.125, exact on tf32 values) ---
    #pragma unroll
    for (int i = 0; i < 8; i++) {
        int lin = tid + i * 128;
        int row = lin >> 4;
        int c4  = lin & 15;
        float4 v = *(const float4*)&qp[(size_t)row * NN + qb + c4 * 4];
        v.x *= 0.125f; v.y *= 0.125f; v.z *= 0.125f; v.w *= 0.125f;
        *(float4*)&QPs[row * PPAD + c4 * 4] = v;
    }
    __syncthreads();

    unsigned qa[8][4];
    const unsigned* QPu = (const unsigned*)QPs;
    #pragma unroll
    for (int kt = 0; kt < 8; kt++) {
        int d0 = kt * 8 + tig;
        int m0 = w * 16 + g;
        qa[kt][0] = QPu[d0 * PPAD + m0];
        qa[kt][1] = QPu[d0 * PPAD + m0 + 8];
        qa[kt][2] = QPu[(d0 + 4) * PPAD + m0];
        qa[kt][3] = QPu[(d0 + 4) * PPAD + m0 + 8];
    }
    __syncthreads();

    float O[8][4];
    #pragma unroll
    for (int t = 0; t < 8; t++)
        #pragma unroll
        for (int r = 0; r < 4; r++) O[t][r] = 0.f;
    float m0r = -INFINITY, m1r = -INFINITY, l0 = 0.f, l1 = 0.f;

    const unsigned* Ku = (const unsigned*)Ks;
    const unsigned* Vu = (const unsigned*)Vs;
    unsigned* Pu = (unsigned*)QPs;

    for (int jt = 0; jt < NN; jt += 64) {
        __syncthreads();
        #pragma unroll
        for (int i = 0; i < 8; i++) {
            int lin = tid + i * 128;
            int row = lin >> 4;
            int c4  = lin & 15;
            *(float4*)&Ks[row * KPAD + c4 * 4] =
                *(const float4*)&kp[(size_t)row * NN + jt + c4 * 4];
            *(float4*)&Vs[row * VPAD + c4 * 4] =
                *(const float4*)&vp[(size_t)row * NN + jt + c4 * 4];
        }
        __syncthreads();

        // --- S = Q K^T ---
        float sc[8][4];
        #pragma unroll
        for (int t = 0; t < 8; t++) {
            sc[t][0] = sc[t][1] = sc[t][2] = sc[t][3] = 0.f;
            #pragma unroll
            for (int kt = 0; kt < 8; kt++) {
                unsigned b0 = Ku[(kt * 8 + tig) * KPAD + t * 8 + g];
                unsigned b1 = Ku[(kt * 8 + tig + 4) * KPAD + t * 8 + g];
                mma_tf32(sc[t], qa[kt], b0, b1);
            }
        }

        // --- Online softmax ---
        float ml0 = -INFINITY, ml1 = -INFINITY;
        #pragma unroll
        for (int t = 0; t < 8; t++) {
            ml0 = fmaxf(ml0, fmaxf(sc[t][0], sc[t][1]));
            ml1 = fmaxf(ml1, fmaxf(sc[t][2], sc[t][3]));
        }
        ml0 = fmaxf(ml0, __shfl_xor_sync(0xffffffffu, ml0, 1));
        ml0 = fmaxf(ml0, __shfl_xor_sync(0xffffffffu, ml0, 2));
        ml1 = fmaxf(ml1, __shfl_xor_sync(0xffffffffu, ml1, 1));
        ml1 = fmaxf(ml1, __shfl_xor_sync(0xffffffffu, ml1, 2));

        const float mn0 = fmaxf(m0r, ml0);
        const float mn1 = fmaxf(m1r, ml1);
        const float corr0 = __expf(m0r - mn0);
        const float corr1 = __expf(m1r - mn1);
        m0r = mn0; m1r = mn1;

        float ls0 = 0.f, ls1 = 0.f;
        const int pr0 = (w * 16 + g) * PPAD;
        const int pr1 = (w * 16 + g + 8) * PPAD;
        #pragma unroll
        for (int t = 0; t < 8; t++) {
            float p0 = __expf(sc[t][0] - mn0);
            float p1 = __expf(sc[t][1] - mn0);
            float p2 = __expf(sc[t][2] - mn1);
            float p3 = __expf(sc[t][3] - mn1);
            ls0 += p0 + p1; ls1 += p2 + p3;
            uint2 a01 = make_uint2(f2tf32(p0), f2tf32(p1));
            uint2 a23 = make_uint2(f2tf32(p2), f2tf32(p3));
            *(uint2*)&Pu[pr0 + t * 8 + 2 * tig] = a01;
            *(uint2*)&Pu[pr1 + t * 8 + 2 * tig] = a23;
        }
        ls0 += __shfl_xor_sync(0xffffffffu, ls0, 1);
        ls0 += __shfl_xor_sync(0xffffffffu, ls0, 2);
        ls1 += __shfl_xor_sync(0xffffffffu, ls1, 1);
        ls1 += __shfl_xor_sync(0xffffffffu, ls1, 2);
        l0 = l0 * corr0 + ls0;
        l1 = l1 * corr1 + ls1;

        #pragma unroll
        for (int t = 0; t < 8; t++) {
            O[t][0] *= corr0; O[t][1] *= corr0;
            O[t][2] *= corr1; O[t][3] *= corr1;
        }
        __syncwarp();

        // --- O += P V^T ---
        #pragma unroll
        for (int kn = 0; kn < 8; kn++) {
            unsigned pa[4];
            pa[0] = Pu[pr0 + kn * 8 + tig];
            pa[1] = Pu[pr1 + kn * 8 + tig];
            pa[2] = Pu[pr0 + kn * 8 + tig + 4];
            pa[3] = Pu[pr1 + kn * 8 + tig + 4];
            #pragma unroll
            for (int dt = 0; dt < 8; dt++) {
                unsigned b0 = Vu[(dt * 8 + g) * VPAD + kn * 8 + tig];
                unsigned b1 = Vu[(dt * 8 + g) * VPAD + kn * 8 + tig + 4];
                mma_tf32(O[dt], pa, b0, b1);
            }
        }
        __syncwarp();
    }

    // --- Epilogue: normalize + round to tf32 + store ---
    const float inv0 = 1.f / l0;
    const float inv1 = 1.f / l1;
    float* op = out + ((size_t)b * CC + hh * DD) * NN;
    const int tok0 = qb + w * 16 + g;
    const int tok1 = tok0 + 8;
    #pragma unroll
    for (int dt = 0; dt < 8; dt++) {
        int d = dt * 8 + 2 * tig;
        op[(size_t)d * NN + tok0]       = tf32r(O[dt][0] * inv0);
        op[(size_t)(d + 1) * NN + tok0] = tf32r(O[dt][1] * inv0);
        op[(size_t)d * NN + tok1]       = tf32r(O[dt][2] * inv1);
        op[(size_t)(d + 1) * NN + tok1] = tf32r(O[dt][3] * inv1);
    }
}

// ---------------------------------------------------------------------------
// Launch
// ---------------------------------------------------------------------------
extern "C" void kernel_launch(void* const* d_in, const int* in_sizes, int n_in,
                              void* d_out, int out_size)
{
    const float* x      = (const float*)d_in[0];
    const float* gn_w   = (const float*)d_in[1];
    const float* gn_b   = (const float*)d_in[2];
    const float* qkv_w  = (const float*)d_in[3];
    const float* qkv_b  = (const float*)d_in[4];
    const float* proj_w = (const float*)d_in[5];
    const float* proj_b = (const float*)d_in[6];
    float* out = (float*)d_out;

    void *p_xn, *p_qkv, *p_att, *p_wq, *p_wp;
    cudaGetSymbolAddress(&p_xn,  g_xn);
    cudaGetSymbolAddress(&p_qkv, g_qkv);
    cudaGetSymbolAddress(&p_att, g_att);
    cudaGetSymbolAddress(&p_wq,  g_wq);
    cudaGetSymbolAddress(&p_wp,  g_wp);
    float* xn  = (float*)p_xn;
    float* qkv = (float*)p_qkv;
    float* att = (float*)p_att;
    float* wq  = (float*)p_wq;
    float* wp  = (float*)p_wp;

    cudaFuncSetAttribute(attn_mma_kernel,
                         cudaFuncAttributeMaxDynamicSharedMemorySize,
                         ATTN_SMEM_BYTES);

    // 0. Round weights to tf32
    wconv_kernel<<<(3 * CC * CC + 255) / 256, 256>>>(qkv_w, proj_w, wq, wp);

    // 1. GroupNorm (tf32-rounded output)
    gn_kernel<<<BB * GG, 1024>>>(x, gn_w, gn_b, xn);

    // 2. QKV GEMM (tf32 tensor): [768,256] x [256,4096], rounded output
    {
        dim3 grid(NN / 128, (3 * CC) / 64, BB);
        gemm_tf32_kernel<<<grid, 256>>>(wq, xn, qkv_b, nullptr, qkv, 3 * CC, 1);
    }

    // 3. Attention (tensor pipe, tf32)
    {
        dim3 grid(NN / 64, BB * NHEAD);
        attn_mma_kernel<<<grid, 128, ATTN_SMEM_BYTES>>>(qkv, att);
    }

    // 4. Proj GEMM (tf32 tensor) + bias + residual, fp32 output
    {
        dim3 grid(NN / 128, CC / 64, BB);
        gemm_tf32_kernel<<<grid, 256>>>(wp, att, proj_b, x, out, CC, 0);
    }
}